// round 5
// baseline (speedup 1.0000x reference)
#include <cuda_runtime.h>
#include <cuda_bf16.h>
#include <cstdint>

#define Bx 4
#define Nx 4096
#define Cx 1024
#define NC3 3072
#define EPSV 1e-15f

// Scratch (device globals — no allocation allowed)
__device__ float    g_qkv[(size_t)Bx * Nx * NC3];      // 192 MB fp32
__device__ uint32_t g_xs[(size_t)Bx * Nx * Cx];        // 64 MB  x split (hi,lo words)
__device__ uint32_t g_atts[(size_t)Bx * Nx * Cx];      // 64 MB  att split
__device__ uint32_t g_wqkvs[(size_t)NC3 * Cx];         // 12 MB  Wqkv split
__device__ uint32_t g_wprojs[(size_t)Cx * Cx];         // 4 MB   Wproj split
__device__ float    g_vkpart[1024 * 1056];
__device__ float    g_vk[128 * 1056];

__device__ __forceinline__ uint32_t smem_u32(const void* p) {
    uint32_t a;
    asm("{ .reg .u64 t; cvta.to.shared.u64 t, %1; cvt.u32.u64 %0, t; }"
        : "=r"(a) : "l"(p));
    return a;
}
__device__ __forceinline__ void cpa16(uint32_t s, const uint32_t* g) {
    asm volatile("cp.async.cg.shared.global [%0], [%1], 16;"
                 :: "r"(s), "l"(g) : "memory");
}
__device__ __forceinline__ void mma_bf16(float d[4], const uint32_t a[4],
                                         uint32_t b0, uint32_t b1) {
    asm("mma.sync.aligned.m16n8k16.row.col.f32.bf16.bf16.f32 "
        "{%0,%1,%2,%3}, {%4,%5,%6,%7}, {%8,%9}, {%0,%1,%2,%3};"
        : "+f"(d[0]), "+f"(d[1]), "+f"(d[2]), "+f"(d[3])
        : "r"(a[0]), "r"(a[1]), "r"(a[2]), "r"(a[3]), "r"(b0), "r"(b1));
}
// pack two fp32 into (hi-word, lo-word) bf16x2 pair: e0 -> low half, e1 -> high
__device__ __forceinline__ void split_pair(float e0, float e1,
                                           uint32_t& hw, uint32_t& lw) {
    __nv_bfloat16 h0 = __float2bfloat16_rn(e0);
    __nv_bfloat16 h1 = __float2bfloat16_rn(e1);
    float r0 = e0 - __bfloat162float(h0);
    float r1 = e1 - __bfloat162float(h1);
    __nv_bfloat16 l0 = __float2bfloat16_rn(r0);
    __nv_bfloat16 l1 = __float2bfloat16_rn(r1);
    __nv_bfloat162 hp = __halves2bfloat162(h0, h1);
    __nv_bfloat162 lp = __halves2bfloat162(l0, l1);
    hw = *(uint32_t*)&hp;
    lw = *(uint32_t*)&lp;
}

// fp32 -> interleaved (hi,lo) bf16x2 words.  npairs = nfloats/2.
__global__ void split_kernel(const float* __restrict__ in,
                             uint32_t* __restrict__ out, int npairs)
{
    int i = blockIdx.x * 256 + threadIdx.x;
    if (i >= npairs) return;
    float2 v = ((const float2*)in)[i];
    uint32_t hw, lw;
    split_pair(v.x, v.y, hw, lw);
    out[2 * i]     = hw;
    out[2 * i + 1] = lw;
}

// ---------------------------------------------------------------------------
// bf16 3-chain tensor GEMM:  C[m,n] = sum_k A[m,k]*W[n,k]  (fp32-grade)
// A, W are pre-split interleaved words: word[2p]=hi pair, word[2p+1]=lo pair.
// CTA 256x128x32, 8 warps, warp tile 64x64, mma.m16n8k16, 2-stage cp.async.
// MODE 0: relu on n < relu_upto.  MODE 1: add bias[n].
// ---------------------------------------------------------------------------
template <int MODE>
__global__ __launch_bounds__(256, 1) void bf16_gemm(
    const uint32_t* __restrict__ A, const uint32_t* __restrict__ W,
    float* __restrict__ C, const float* __restrict__ bias,
    int M, int Nn, int K, int relu_upto)
{
    constexpr int SROW = 36;                      // 32 used words + 4 pad
    constexpr int AROWS = 256, BROWS = 128;
    constexpr int STAGEW = (AROWS + BROWS) * SROW;
    extern __shared__ uint32_t sm[];
    const uint32_t sb = smem_u32(sm);

    const int tid = threadIdx.x;
    const int wid = tid >> 5;
    const int lane = tid & 31;
    const int g = lane >> 2;
    const int tig = lane & 3;
    const int warp_m = (wid & 3) * 64;
    const int warp_n = (wid >> 2) * 64;
    const int m0 = blockIdx.y * 256;
    const int n0 = blockIdx.x * 128;

    const uint32_t* Ab = A + (size_t)m0 * K;      // K words per row
    const uint32_t* Wb = W + (size_t)n0 * K;

    float acc[4][8][4];
#pragma unroll
    for (int mt = 0; mt < 4; mt++)
#pragma unroll
        for (int nt = 0; nt < 8; nt++)
#pragma unroll
            for (int j = 0; j < 4; j++) acc[mt][nt][j] = 0.0f;

    const int NK = K / 32;                        // 32 words per k-tile
    const int crow = tid >> 3;
    const int ccol = (tid & 7) * 4;

    auto issue = [&](int it, int s) {
        const int kt = it * 32;
        const uint32_t as = sb + (uint32_t)s * STAGEW * 4;
        const uint32_t bs = as + AROWS * SROW * 4;
#pragma unroll
        for (int i = 0; i < 8; i++) {
            int row = crow + i * 32;
            cpa16(as + (uint32_t)(row * SROW + ccol) * 4,
                  Ab + (size_t)row * K + kt + ccol);
        }
#pragma unroll
        for (int i = 0; i < 4; i++) {
            int row = crow + i * 32;
            cpa16(bs + (uint32_t)(row * SROW + ccol) * 4,
                  Wb + (size_t)row * K + kt + ccol);
        }
        asm volatile("cp.async.commit_group;" ::: "memory");
    };

    issue(0, 0);

    for (int it = 0; it < NK; it++) {
        if (it + 1 < NK) {
            issue(it + 1, (it + 1) & 1);
            asm volatile("cp.async.wait_group 1;" ::: "memory");
        } else {
            asm volatile("cp.async.wait_group 0;" ::: "memory");
        }
        __syncthreads();

        const uint32_t* sA = sm + (it & 1) * STAGEW;
        const uint32_t* sB = sA + AROWS * SROW;

#pragma unroll
        for (int kk = 0; kk < 2; kk++) {
            uint32_t ah[4][4], al[4][4];
#pragma unroll
            for (int mt = 0; mt < 4; mt++) {
                int r0 = (warp_m + mt * 16 + g) * SROW + kk * 16 + 2 * tig;
                uint2 t0 = *(const uint2*)(sA + r0);
                uint2 t1 = *(const uint2*)(sA + r0 + 8 * SROW);
                uint2 t2 = *(const uint2*)(sA + r0 + 8);
                uint2 t3 = *(const uint2*)(sA + r0 + 8 * SROW + 8);
                ah[mt][0] = t0.x; ah[mt][1] = t1.x; ah[mt][2] = t2.x; ah[mt][3] = t3.x;
                al[mt][0] = t0.y; al[mt][1] = t1.y; al[mt][2] = t2.y; al[mt][3] = t3.y;
            }
            uint32_t bh[8][2], bl[8][2];
#pragma unroll
            for (int nt = 0; nt < 8; nt++) {
                int rb = (warp_n + nt * 8 + g) * SROW + kk * 16 + 2 * tig;
                uint2 u0 = *(const uint2*)(sB + rb);
                uint2 u1 = *(const uint2*)(sB + rb + 8);
                bh[nt][0] = u0.x; bh[nt][1] = u1.x;
                bl[nt][0] = u0.y; bl[nt][1] = u1.y;
            }
            // chain 0: ah*bh — then ah*bl — then al*bh (acc reuse 32 apart)
#pragma unroll
            for (int nt = 0; nt < 8; nt++)
#pragma unroll
                for (int mt = 0; mt < 4; mt++)
                    mma_bf16(acc[mt][nt], ah[mt], bh[nt][0], bh[nt][1]);
#pragma unroll
            for (int nt = 0; nt < 8; nt++)
#pragma unroll
                for (int mt = 0; mt < 4; mt++)
                    mma_bf16(acc[mt][nt], ah[mt], bl[nt][0], bl[nt][1]);
#pragma unroll
            for (int nt = 0; nt < 8; nt++)
#pragma unroll
                for (int mt = 0; mt < 4; mt++)
                    mma_bf16(acc[mt][nt], al[mt], bh[nt][0], bh[nt][1]);
        }
        __syncthreads();
    }

    // epilogue (fp32 out)
#pragma unroll
    for (int mt = 0; mt < 4; mt++) {
        int mA = m0 + warp_m + mt * 16 + g;
#pragma unroll
        for (int nt = 0; nt < 8; nt++) {
            int n = n0 + warp_n + nt * 8 + 2 * tig;
            float e0 = acc[mt][nt][0], e1 = acc[mt][nt][1];
            float e2 = acc[mt][nt][2], e3 = acc[mt][nt][3];
            if (MODE == 0) {
                if (n < relu_upto)     { e0 = fmaxf(e0, 0.f); e2 = fmaxf(e2, 0.f); }
                if (n + 1 < relu_upto) { e1 = fmaxf(e1, 0.f); e3 = fmaxf(e3, 0.f); }
            } else {
                float bb0 = bias[n], bb1 = bias[n + 1];
                e0 += bb0; e1 += bb1; e2 += bb0; e3 += bb1;
            }
            *(float2*)(C + (size_t)mA * Nn + n)       = make_float2(e0, e1);
            *(float2*)(C + (size_t)(mA + 8) * Nn + n) = make_float2(e2, e3);
        }
    }
}

// ---------------------------------------------------------------------------
// vk partial reduction (unchanged)
// ---------------------------------------------------------------------------
__global__ __launch_bounds__(256) void vk_partial_kernel(
    const float* __restrict__ qkv, float* __restrict__ part)
{
    const int blk = blockIdx.x;
    const int slice = blk & 7;
    const int head = blk >> 3;
    const int b = head >> 5;
    const int hh = head & 31;
    const int tid = threadIdx.x;

    __shared__ float ks[8][32];
    __shared__ float vs[8][32];

    float acc[5] = {0.f, 0.f, 0.f, 0.f, 0.f};

    const float* base = qkv + (size_t)b * Nx * NC3 + (size_t)(slice * 512) * NC3 + hh * 32;
    const int r = tid >> 5;
    const int e = tid & 31;

    for (int n0 = 0; n0 < 512; n0 += 8) {
        const float* p = base + (size_t)(n0 + r) * NC3 + e;
        float kreg = p[1024];
        float vreg = p[2048];
        __syncthreads();
        ks[r][e] = kreg;
        vs[r][e] = vreg;
        __syncthreads();
#pragma unroll
        for (int rr = 0; rr < 8; rr++) {
#pragma unroll
            for (int i = 0; i < 5; i++) {
                int idx = tid + 256 * i;
                if (idx < 1056) {
                    int d = idx >> 5;
                    int ee = idx & 31;
                    float vval = (d == 32) ? 1.0f : vs[rr][d];
                    acc[i] += vval * ks[rr][ee];
                }
            }
        }
    }
#pragma unroll
    for (int i = 0; i < 5; i++) {
        int idx = tid + 256 * i;
        if (idx < 1056) part[(size_t)blk * 1056 + idx] = acc[i];
    }
}

__global__ void vk_reduce_kernel(const float* __restrict__ part,
                                 float* __restrict__ vk)
{
    int idx = blockIdx.x * 256 + threadIdx.x;
    if (idx >= 128 * 1056) return;
    int head = idx / 1056;
    int j = idx % 1056;
    float s = 0.f;
#pragma unroll
    for (int sl = 0; sl < 8; sl++)
        s += part[(size_t)(head * 8 + sl) * 1056 + j];
    vk[idx] = s;
}

// ---------------------------------------------------------------------------
// att kernel: normalize and write SPLIT bf16 hi/lo words directly (GEMM2 A)
// ---------------------------------------------------------------------------
__global__ __launch_bounds__(128) void att_kernel(
    const float* __restrict__ qkv, const float* __restrict__ vk,
    uint32_t* __restrict__ atts)
{
    const int blk = blockIdx.x;
    const int nch = blk & 31;
    const int head = blk >> 5;
    const int b = head >> 5;
    const int hh = head & 31;
    const int tid = threadIdx.x;

    __shared__ float vks[1056];
    __shared__ uint32_t su[128][33];

    for (int i = tid; i < 1056; i += 128)
        vks[i] = vk[(size_t)head * 1056 + i];

    const float* qbase = qkv + (size_t)b * Nx * NC3 + (size_t)(nch * 128) * NC3 + hh * 32;
#pragma unroll
    for (int i = 0; i < 32; i++) {
        int idx = i * 128 + tid;
        int row = idx >> 5;
        int e = idx & 31;
        ((float*)su)[row * 33 + e] = qbase[(size_t)row * NC3 + e];
    }
    __syncthreads();

    float qr[32];
#pragma unroll
    for (int e = 0; e < 32; e++) qr[e] = ((float*)su)[tid * 33 + e];

    float den = 0.f;
#pragma unroll
    for (int e = 0; e < 32; e++) den += vks[1024 + e] * qr[e];
    float inv = 1.0f / (den + EPSV);

    float outv[32];
#pragma unroll
    for (int d = 0; d < 32; d++) {
        float s = 0.f;
#pragma unroll
        for (int e = 0; e < 32; e++) s += vks[d * 32 + e] * qr[e];
        outv[d] = s * inv;
    }
    __syncthreads();
    // stage split words: 16 pairs -> 32 words per row
#pragma unroll
    for (int w = 0; w < 16; w++) {
        uint32_t hw, lw;
        split_pair(outv[2 * w], outv[2 * w + 1], hw, lw);
        su[tid][2 * w]     = hw;
        su[tid][2 * w + 1] = lw;
    }
    __syncthreads();

    // coalesced write: token rows x 32 words at channel-word base hh*32
    uint32_t* obase = atts + ((size_t)b * Nx + (size_t)nch * 128) * Cx + hh * 32;
#pragma unroll
    for (int i = 0; i < 32; i++) {
        int idx = i * 128 + tid;
        int row = idx >> 5;
        int w = idx & 31;
        obase[(size_t)row * Cx + w] = su[row][w];
    }
}

// ---------------------------------------------------------------------------
extern "C" void kernel_launch(void* const* d_in, const int* in_sizes, int n_in,
                              void* d_out, int out_size)
{
    const float* x     = (const float*)d_in[0];
    const float* Wqkv  = (const float*)d_in[1];
    const float* Wproj = (const float*)d_in[2];
    const float* bproj = (const float*)d_in[3];
    float* out = (float*)d_out;

    float *qkv, *part, *vk;
    uint32_t *xs, *atts, *wqkvs, *wprojs;
    cudaGetSymbolAddress((void**)&qkv,    g_qkv);
    cudaGetSymbolAddress((void**)&part,   g_vkpart);
    cudaGetSymbolAddress((void**)&vk,     g_vk);
    cudaGetSymbolAddress((void**)&xs,     g_xs);
    cudaGetSymbolAddress((void**)&atts,   g_atts);
    cudaGetSymbolAddress((void**)&wqkvs,  g_wqkvs);
    cudaGetSymbolAddress((void**)&wprojs, g_wprojs);

    const int M = Bx * Nx;   // 16384

    const int smem = 2 * (256 + 128) * 36 * 4;   // 110592 B
    cudaFuncSetAttribute(bf16_gemm<0>,
                         cudaFuncAttributeMaxDynamicSharedMemorySize, smem);
    cudaFuncSetAttribute(bf16_gemm<1>,
                         cudaFuncAttributeMaxDynamicSharedMemorySize, smem);

    // 0) split inputs into bf16 hi/lo interleaved words
    {
        int np;
        np = M * Cx / 2;
        split_kernel<<<(np + 255) / 256, 256>>>(x, xs, np);
        np = NC3 * Cx / 2;
        split_kernel<<<(np + 255) / 256, 256>>>(Wqkv, wqkvs, np);
        np = Cx * Cx / 2;
        split_kernel<<<(np + 255) / 256, 256>>>(Wproj, wprojs, np);
    }

    // 1) qkv = x @ Wqkv^T (bf16 3-chain), relu on n < 2048
    bf16_gemm<0><<<dim3(NC3 / 128, M / 256), 256, smem>>>(
        xs, wqkvs, qkv, nullptr, M, NC3, Cx, 2 * Cx);

    // 2) vk partials + reduce
    vk_partial_kernel<<<1024, 256>>>(qkv, part);
    vk_reduce_kernel<<<(128 * 1056 + 255) / 256, 256>>>(part, vk);

    // 3) attention normalize -> atts (split bf16)
    att_kernel<<<4096, 128>>>(qkv, vk, atts);

    // 4) out = att @ Wproj^T + b  (bf16 3-chain)
    bf16_gemm<1><<<dim3(Cx / 128, M / 256), 256, smem>>>(
        atts, wprojs, out, bproj, M, Cx, Cx, 0);
}

// round 6
// speedup vs baseline: 1.1381x; 1.1381x over previous
#include <cuda_runtime.h>
#include <cuda_bf16.h>
#include <cstdint>

#define Bx 4
#define Nx 4096
#define Cx 1024
#define NC3 3072
#define EPSV 1e-15f

// Scratch (device globals — no allocation allowed).  Split planes hold bf16
// pairs packed in uint32 words (2 elems/word), row-major [rows][K/2 words].
__device__ float    g_qkv[(size_t)Bx * Nx * NC3];          // 192 MB fp32
__device__ uint32_t g_xh[(size_t)Bx * Nx * Cx / 2];        // x hi plane
__device__ uint32_t g_xl[(size_t)Bx * Nx * Cx / 2];        // x lo plane
__device__ uint32_t g_ath[(size_t)Bx * Nx * Cx / 2];       // att hi
__device__ uint32_t g_atl[(size_t)Bx * Nx * Cx / 2];       // att lo
__device__ uint32_t g_wqh[(size_t)NC3 * Cx / 2];
__device__ uint32_t g_wql[(size_t)NC3 * Cx / 2];
__device__ uint32_t g_wph[(size_t)Cx * Cx / 2];
__device__ uint32_t g_wpl[(size_t)Cx * Cx / 2];
__device__ float    g_vkpart[1024 * 1056];
__device__ float    g_vk[128 * 1056];

__device__ __forceinline__ uint32_t smem_u32(const void* p) {
    uint32_t a;
    asm("{ .reg .u64 t; cvta.to.shared.u64 t, %1; cvt.u32.u64 %0, t; }"
        : "=r"(a) : "l"(p));
    return a;
}
__device__ __forceinline__ void cpa16(uint32_t s, const void* g) {
    asm volatile("cp.async.cg.shared.global [%0], [%1], 16;"
                 :: "r"(s), "l"(g) : "memory");
}
__device__ __forceinline__ void ldsm4(uint32_t& r0, uint32_t& r1,
                                      uint32_t& r2, uint32_t& r3, uint32_t a) {
    asm volatile("ldmatrix.sync.aligned.m8n8.x4.shared.b16 {%0,%1,%2,%3}, [%4];"
                 : "=r"(r0), "=r"(r1), "=r"(r2), "=r"(r3) : "r"(a));
}
__device__ __forceinline__ void mma_bf16(float d[4], const uint32_t a[4],
                                         uint32_t b0, uint32_t b1) {
    asm("mma.sync.aligned.m16n8k16.row.col.f32.bf16.bf16.f32 "
        "{%0,%1,%2,%3}, {%4,%5,%6,%7}, {%8,%9}, {%0,%1,%2,%3};"
        : "+f"(d[0]), "+f"(d[1]), "+f"(d[2]), "+f"(d[3])
        : "r"(a[0]), "r"(a[1]), "r"(a[2]), "r"(a[3]), "r"(b0), "r"(b1));
}
__device__ __forceinline__ void split_pair(float e0, float e1,
                                           uint32_t& hw, uint32_t& lw) {
    __nv_bfloat16 h0 = __float2bfloat16_rn(e0);
    __nv_bfloat16 h1 = __float2bfloat16_rn(e1);
    float r0 = e0 - __bfloat162float(h0);
    float r1 = e1 - __bfloat162float(h1);
    __nv_bfloat16 l0 = __float2bfloat16_rn(r0);
    __nv_bfloat16 l1 = __float2bfloat16_rn(r1);
    __nv_bfloat162 hp = __halves2bfloat162(h0, h1);
    __nv_bfloat162 lp = __halves2bfloat162(l0, l1);
    hw = *(uint32_t*)&hp;
    lw = *(uint32_t*)&lp;
}

// fp32 -> separate hi/lo bf16 planes
__global__ void split_kernel(const float* __restrict__ in,
                             uint32_t* __restrict__ oh,
                             uint32_t* __restrict__ ol, int npairs)
{
    int i = blockIdx.x * 256 + threadIdx.x;
    if (i >= npairs) return;
    float2 v = ((const float2*)in)[i];
    uint32_t hw, lw;
    split_pair(v.x, v.y, hw, lw);
    oh[i] = hw;
    ol[i] = lw;
}

// ---------------------------------------------------------------------------
// bf16 3-chain tensor GEMM:  C[m,n] = sum_k A[m,k]*W[n,k]  (fp32-grade)
// A/W given as separate hi/lo bf16 planes. CTA 256x128x32, 8 warps,
// warp tile 64x64, ldmatrix fragments, 3-stage cp.async, 1 sync per k-tile.
// MODE 0: relu on n < relu_upto.  MODE 1: add bias[n].
// ---------------------------------------------------------------------------
template <int MODE>
__global__ __launch_bounds__(256, 1) void bf16_gemm(
    const uint32_t* __restrict__ Ah_, const uint32_t* __restrict__ Al_,
    const uint32_t* __restrict__ Wh_, const uint32_t* __restrict__ Wl_,
    float* __restrict__ C, const float* __restrict__ bias,
    int M, int Nn, int K, int relu_upto)
{
    // stage layout (bytes): Ah[256x80] Al[256x80] Bh[128x80] Bl[128x80]
    constexpr int PITCH = 80;
    constexpr int A_TILE = 256 * PITCH;          // 20480
    constexpr int B_TILE = 128 * PITCH;          // 10240
    constexpr int OFF_AL = A_TILE;
    constexpr int OFF_BH = 2 * A_TILE;
    constexpr int OFF_BL = 2 * A_TILE + B_TILE;
    constexpr int STAGE = 2 * A_TILE + 2 * B_TILE;   // 61440
    extern __shared__ char smem[];
    const uint32_t sb = smem_u32(smem);

    const int tid = threadIdx.x;
    const int wid = tid >> 5;
    const int lane = tid & 31;
    const int g = lane >> 2;
    const int tig = lane & 3;
    const int warp_m = (wid & 3) * 64;
    const int warp_n = (wid >> 2) * 64;
    const int m0 = blockIdx.y * 256;
    const int n0 = blockIdx.x * 128;

    const __nv_bfloat16* Ah = (const __nv_bfloat16*)Ah_;
    const __nv_bfloat16* Al = (const __nv_bfloat16*)Al_;
    const __nv_bfloat16* Wh = (const __nv_bfloat16*)Wh_;
    const __nv_bfloat16* Wl = (const __nv_bfloat16*)Wl_;

    float acc[4][8][4];
#pragma unroll
    for (int mt = 0; mt < 4; mt++)
#pragma unroll
        for (int nt = 0; nt < 8; nt++)
#pragma unroll
            for (int j = 0; j < 4; j++) acc[mt][nt][j] = 0.0f;

    const int NK = K / 32;
    const int crow = tid >> 2;                   // 0..63
    const int cchk = tid & 3;                    // 16B chunk

    auto issue = [&](int it, int s) {
        const int kt = it * 32 + cchk * 8;       // elem offset
        const uint32_t st = sb + (uint32_t)s * STAGE;
#pragma unroll
        for (int i = 0; i < 4; i++) {
            int r = crow + i * 64;
            uint32_t so = (uint32_t)(r * PITCH + cchk * 16);
            const size_t go = (size_t)(m0 + r) * K + kt;
            cpa16(st + so, Ah + go);
            cpa16(st + OFF_AL + so, Al + go);
        }
#pragma unroll
        for (int i = 0; i < 2; i++) {
            int r = crow + i * 64;
            uint32_t so = (uint32_t)(r * PITCH + cchk * 16);
            const size_t go = (size_t)(n0 + r) * K + kt;
            cpa16(st + OFF_BH + so, Wh + go);
            cpa16(st + OFF_BL + so, Wl + go);
        }
        asm volatile("cp.async.commit_group;" ::: "memory");
    };

    issue(0, 0);
    if (NK > 1) issue(1, 1);

    const uint32_t lrow = (uint32_t)(lane & 15);
    const uint32_t lchk = (uint32_t)(lane >> 4) * 16;

    for (int it = 0; it < NK; it++) {
        if (it + 1 < NK) {
            asm volatile("cp.async.wait_group 1;" ::: "memory");
        } else {
            asm volatile("cp.async.wait_group 0;" ::: "memory");
        }
        __syncthreads();
        if (it + 2 < NK) issue(it + 2, (it + 2) % 3);

        const uint32_t st = sb + (uint32_t)(it % 3) * STAGE;
        const uint32_t abase = st + (uint32_t)(warp_m + lrow) * PITCH + lchk;
        const uint32_t bbase = st + OFF_BH + (uint32_t)(warp_n + lrow) * PITCH + lchk;

#pragma unroll
        for (int kk = 0; kk < 2; kk++) {
            uint32_t ah[4][4], al[4][4];
#pragma unroll
            for (int mt = 0; mt < 4; mt++) {
                uint32_t ao = abase + (uint32_t)(mt * 16 * PITCH + kk * 32);
                ldsm4(ah[mt][0], ah[mt][1], ah[mt][2], ah[mt][3], ao);
                ldsm4(al[mt][0], al[mt][1], al[mt][2], al[mt][3], ao + OFF_AL);
            }
            uint32_t bh[8][2], bl[8][2];
#pragma unroll
            for (int p = 0; p < 4; p++) {
                uint32_t bo = bbase + (uint32_t)(p * 16 * PITCH + kk * 32);
                uint32_t r0, r1, r2, r3;
                ldsm4(r0, r1, r2, r3, bo);
                bh[2 * p][0] = r0; bh[2 * p][1] = r2;
                bh[2 * p + 1][0] = r1; bh[2 * p + 1][1] = r3;
                ldsm4(r0, r1, r2, r3, bo + (OFF_BL - OFF_BH));
                bl[2 * p][0] = r0; bl[2 * p][1] = r2;
                bl[2 * p + 1][0] = r1; bl[2 * p + 1][1] = r3;
            }
#pragma unroll
            for (int nt = 0; nt < 8; nt++)
#pragma unroll
                for (int mt = 0; mt < 4; mt++)
                    mma_bf16(acc[mt][nt], ah[mt], bh[nt][0], bh[nt][1]);
#pragma unroll
            for (int nt = 0; nt < 8; nt++)
#pragma unroll
                for (int mt = 0; mt < 4; mt++)
                    mma_bf16(acc[mt][nt], ah[mt], bl[nt][0], bl[nt][1]);
#pragma unroll
            for (int nt = 0; nt < 8; nt++)
#pragma unroll
                for (int mt = 0; mt < 4; mt++)
                    mma_bf16(acc[mt][nt], al[mt], bh[nt][0], bh[nt][1]);
        }
    }

    // epilogue (fp32 out)
#pragma unroll
    for (int mt = 0; mt < 4; mt++) {
        int mA = m0 + warp_m + mt * 16 + g;
#pragma unroll
        for (int nt = 0; nt < 8; nt++) {
            int n = n0 + warp_n + nt * 8 + 2 * tig;
            float e0 = acc[mt][nt][0], e1 = acc[mt][nt][1];
            float e2 = acc[mt][nt][2], e3 = acc[mt][nt][3];
            if (MODE == 0) {
                if (n < relu_upto)     { e0 = fmaxf(e0, 0.f); e2 = fmaxf(e2, 0.f); }
                if (n + 1 < relu_upto) { e1 = fmaxf(e1, 0.f); e3 = fmaxf(e3, 0.f); }
            } else {
                float bb0 = bias[n], bb1 = bias[n + 1];
                e0 += bb0; e1 += bb1; e2 += bb0; e3 += bb1;
            }
            *(float2*)(C + (size_t)mA * Nn + n)       = make_float2(e0, e1);
            *(float2*)(C + (size_t)(mA + 8) * Nn + n) = make_float2(e2, e3);
        }
    }
}

// ---------------------------------------------------------------------------
// vk partial reduction (unchanged)
// ---------------------------------------------------------------------------
__global__ __launch_bounds__(256) void vk_partial_kernel(
    const float* __restrict__ qkv, float* __restrict__ part)
{
    const int blk = blockIdx.x;
    const int slice = blk & 7;
    const int head = blk >> 3;
    const int b = head >> 5;
    const int hh = head & 31;
    const int tid = threadIdx.x;

    __shared__ float ks[8][32];
    __shared__ float vs[8][32];

    float acc[5] = {0.f, 0.f, 0.f, 0.f, 0.f};

    const float* base = qkv + (size_t)b * Nx * NC3 + (size_t)(slice * 512) * NC3 + hh * 32;
    const int r = tid >> 5;
    const int e = tid & 31;

    for (int n0 = 0; n0 < 512; n0 += 8) {
        const float* p = base + (size_t)(n0 + r) * NC3 + e;
        float kreg = p[1024];
        float vreg = p[2048];
        __syncthreads();
        ks[r][e] = kreg;
        vs[r][e] = vreg;
        __syncthreads();
#pragma unroll
        for (int rr = 0; rr < 8; rr++) {
#pragma unroll
            for (int i = 0; i < 5; i++) {
                int idx = tid + 256 * i;
                if (idx < 1056) {
                    int d = idx >> 5;
                    int ee = idx & 31;
                    float vval = (d == 32) ? 1.0f : vs[rr][d];
                    acc[i] += vval * ks[rr][ee];
                }
            }
        }
    }
#pragma unroll
    for (int i = 0; i < 5; i++) {
        int idx = tid + 256 * i;
        if (idx < 1056) part[(size_t)blk * 1056 + idx] = acc[i];
    }
}

__global__ void vk_reduce_kernel(const float* __restrict__ part,
                                 float* __restrict__ vk)
{
    int idx = blockIdx.x * 256 + threadIdx.x;
    if (idx >= 128 * 1056) return;
    int head = idx / 1056;
    int j = idx % 1056;
    float s = 0.f;
#pragma unroll
    for (int sl = 0; sl < 8; sl++)
        s += part[(size_t)(head * 8 + sl) * 1056 + j];
    vk[idx] = s;
}

// ---------------------------------------------------------------------------
// att kernel: normalize and write split hi/lo bf16 planes (GEMM2 A operand)
// ---------------------------------------------------------------------------
__global__ __launch_bounds__(128) void att_kernel(
    const float* __restrict__ qkv, const float* __restrict__ vk,
    uint32_t* __restrict__ ath, uint32_t* __restrict__ atl)
{
    const int blk = blockIdx.x;
    const int nch = blk & 31;
    const int head = blk >> 5;
    const int b = head >> 5;
    const int hh = head & 31;
    const int tid = threadIdx.x;

    __shared__ float vks[1056];
    __shared__ float qs[128][33];
    __shared__ uint32_t sh[128][17];
    __shared__ uint32_t sl[128][17];

    for (int i = tid; i < 1056; i += 128)
        vks[i] = vk[(size_t)head * 1056 + i];

    const float* qbase = qkv + (size_t)b * Nx * NC3 + (size_t)(nch * 128) * NC3 + hh * 32;
#pragma unroll
    for (int i = 0; i < 32; i++) {
        int idx = i * 128 + tid;
        int row = idx >> 5;
        int e = idx & 31;
        qs[row][e] = qbase[(size_t)row * NC3 + e];
    }
    __syncthreads();

    float qr[32];
#pragma unroll
    for (int e = 0; e < 32; e++) qr[e] = qs[tid][e];

    float den = 0.f;
#pragma unroll
    for (int e = 0; e < 32; e++) den += vks[1024 + e] * qr[e];
    float inv = 1.0f / (den + EPSV);

#pragma unroll
    for (int w = 0; w < 16; w++) {
        float s0 = 0.f, s1 = 0.f;
#pragma unroll
        for (int e = 0; e < 32; e++) {
            s0 += vks[(2 * w) * 32 + e] * qr[e];
            s1 += vks[(2 * w + 1) * 32 + e] * qr[e];
        }
        uint32_t hw, lw;
        split_pair(s0 * inv, s1 * inv, hw, lw);
        sh[tid][w] = hw;
        sl[tid][w] = lw;
    }
    __syncthreads();

    // coalesced plane writes: [row][512 words], head block at hh*16
    const size_t rowbase = (size_t)b * Nx + (size_t)nch * 128;
#pragma unroll
    for (int i = 0; i < 16; i++) {
        int idx = i * 128 + tid;
        int row = idx >> 4;
        int w = idx & 15;
        size_t o = (rowbase + row) * 512 + hh * 16 + w;
        ath[o] = sh[row][w];
        atl[o] = sl[row][w];
    }
}

// ---------------------------------------------------------------------------
extern "C" void kernel_launch(void* const* d_in, const int* in_sizes, int n_in,
                              void* d_out, int out_size)
{
    const float* x     = (const float*)d_in[0];
    const float* Wqkv  = (const float*)d_in[1];
    const float* Wproj = (const float*)d_in[2];
    const float* bproj = (const float*)d_in[3];
    float* out = (float*)d_out;

    float *qkv, *part, *vk;
    uint32_t *xh, *xl, *ath, *atl, *wqh, *wql, *wph, *wpl;
    cudaGetSymbolAddress((void**)&qkv,  g_qkv);
    cudaGetSymbolAddress((void**)&part, g_vkpart);
    cudaGetSymbolAddress((void**)&vk,   g_vk);
    cudaGetSymbolAddress((void**)&xh,   g_xh);
    cudaGetSymbolAddress((void**)&xl,   g_xl);
    cudaGetSymbolAddress((void**)&ath,  g_ath);
    cudaGetSymbolAddress((void**)&atl,  g_atl);
    cudaGetSymbolAddress((void**)&wqh,  g_wqh);
    cudaGetSymbolAddress((void**)&wql,  g_wql);
    cudaGetSymbolAddress((void**)&wph,  g_wph);
    cudaGetSymbolAddress((void**)&wpl,  g_wpl);

    const int M = Bx * Nx;   // 16384

    const int smem = 3 * 61440;   // 184320 B
    cudaFuncSetAttribute(bf16_gemm<0>,
                         cudaFuncAttributeMaxDynamicSharedMemorySize, smem);
    cudaFuncSetAttribute(bf16_gemm<1>,
                         cudaFuncAttributeMaxDynamicSharedMemorySize, smem);

    // 0) split inputs into hi/lo bf16 planes
    {
        int np;
        np = M * Cx / 2;
        split_kernel<<<(np + 255) / 256, 256>>>(x, xh, xl, np);
        np = NC3 * Cx / 2;
        split_kernel<<<(np + 255) / 256, 256>>>(Wqkv, wqh, wql, np);
        np = Cx * Cx / 2;
        split_kernel<<<(np + 255) / 256, 256>>>(Wproj, wph, wpl, np);
    }

    // 1) qkv = x @ Wqkv^T (bf16 3-chain), relu on n < 2048
    bf16_gemm<0><<<dim3(NC3 / 128, M / 256), 256, smem>>>(
        xh, xl, wqh, wql, qkv, nullptr, M, NC3, Cx, 2 * Cx);

    // 2) vk partials + reduce
    vk_partial_kernel<<<1024, 256>>>(qkv, part);
    vk_reduce_kernel<<<(128 * 1056 + 255) / 256, 256>>>(part, vk);

    // 3) attention normalize -> att hi/lo planes
    att_kernel<<<4096, 128>>>(qkv, vk, ath, atl);

    // 4) out = att @ Wproj^T + b  (bf16 3-chain)
    bf16_gemm<1><<<dim3(Cx / 128, M / 256), 256, smem>>>(
        ath, atl, wph, wpl, out, bproj, M, Cx, Cx, 0);
}

// round 7
// speedup vs baseline: 1.6680x; 1.4656x over previous
#include <cuda_runtime.h>
#include <cuda_fp16.h>
#include <cstdint>

#define Bx 4
#define Nx 4096
#define Cx 1024
#define NC3 3072
#define EPSV 1e-15f

// Scratch (device globals — no allocation allowed).  fp16 planes pack 2
// elems per uint32 word, row-major [rows][K/2 words].
__device__ float    g_qkv[(size_t)Bx * Nx * NC3];          // 192 MB fp32
__device__ uint32_t g_xh[(size_t)Bx * Nx * Cx / 2];        // x hi plane
__device__ uint32_t g_xl[(size_t)Bx * Nx * Cx / 2];        // x lo plane
__device__ uint32_t g_ath[(size_t)Bx * Nx * Cx / 2];       // att hi
__device__ uint32_t g_atl[(size_t)Bx * Nx * Cx / 2];       // att lo
__device__ uint32_t g_wqh[(size_t)NC3 * Cx / 2];           // Wqkv (single fp16)
__device__ uint32_t g_wph[(size_t)Cx * Cx / 2];            // Wproj (single fp16)
__device__ float    g_vkpart[1024 * 1056];
__device__ float    g_vk[128 * 1056];

__device__ __forceinline__ uint32_t smem_u32(const void* p) {
    uint32_t a;
    asm("{ .reg .u64 t; cvta.to.shared.u64 t, %1; cvt.u32.u64 %0, t; }"
        : "=r"(a) : "l"(p));
    return a;
}
__device__ __forceinline__ void cpa16(uint32_t s, const void* g) {
    asm volatile("cp.async.cg.shared.global [%0], [%1], 16;"
                 :: "r"(s), "l"(g) : "memory");
}
__device__ __forceinline__ void ldsm4(uint32_t& r0, uint32_t& r1,
                                      uint32_t& r2, uint32_t& r3, uint32_t a) {
    asm volatile("ldmatrix.sync.aligned.m8n8.x4.shared.b16 {%0,%1,%2,%3}, [%4];"
                 : "=r"(r0), "=r"(r1), "=r"(r2), "=r"(r3) : "r"(a));
}
__device__ __forceinline__ void mma_f16(float d[4], const uint32_t a[4],
                                        uint32_t b0, uint32_t b1) {
    asm("mma.sync.aligned.m16n8k16.row.col.f32.f16.f16.f32 "
        "{%0,%1,%2,%3}, {%4,%5,%6,%7}, {%8,%9}, {%0,%1,%2,%3};"
        : "+f"(d[0]), "+f"(d[1]), "+f"(d[2]), "+f"(d[3])
        : "r"(a[0]), "r"(a[1]), "r"(a[2]), "r"(a[3]), "r"(b0), "r"(b1));
}
// split two fp32 into fp16 (hi word, lo word) pairs
__device__ __forceinline__ void split_pair(float e0, float e1,
                                           uint32_t& hw, uint32_t& lw) {
    __half h0 = __float2half_rn(e0);
    __half h1 = __float2half_rn(e1);
    float r0 = e0 - __half2float(h0);
    float r1 = e1 - __half2float(h1);
    __half2 hp = __halves2half2(h0, h1);
    __half2 lp = __halves2half2(__float2half_rn(r0), __float2half_rn(r1));
    hw = *(uint32_t*)&hp;
    lw = *(uint32_t*)&lp;
}

__global__ void split2_kernel(const float* __restrict__ in,
                              uint32_t* __restrict__ oh,
                              uint32_t* __restrict__ ol, int npairs)
{
    int i = blockIdx.x * 256 + threadIdx.x;
    if (i >= npairs) return;
    float2 v = ((const float2*)in)[i];
    uint32_t hw, lw;
    split_pair(v.x, v.y, hw, lw);
    oh[i] = hw;
    ol[i] = lw;
}

__global__ void round1_kernel(const float* __restrict__ in,
                              uint32_t* __restrict__ oh, int npairs)
{
    int i = blockIdx.x * 256 + threadIdx.x;
    if (i >= npairs) return;
    float2 v = ((const float2*)in)[i];
    __half2 hp = __halves2half2(__float2half_rn(v.x), __float2half_rn(v.y));
    oh[i] = *(uint32_t*)&hp;
}

// ---------------------------------------------------------------------------
// fp16 A-split 2-chain GEMM:  C[m,n] = sum_k A[m,k]*W[n,k]
// A given as hi/lo fp16 planes (exact to ~22 bits); W single-rounded fp16.
// CTA 128x128x32, 8 warps, warp tile 32x64, ldmatrix, 3-stage cp.async,
// 2 CTAs/SM.  MODE 0: relu on n < relu_upto.  MODE 1: add bias[n].
// ---------------------------------------------------------------------------
template <int MODE>
__global__ __launch_bounds__(256, 2) void f16_gemm(
    const uint32_t* __restrict__ Ah_, const uint32_t* __restrict__ Al_,
    const uint32_t* __restrict__ Wh_,
    float* __restrict__ C, const float* __restrict__ bias,
    int M, int Nn, int K, int relu_upto)
{
    // stage layout (bytes): Ah[128x80] Al[128x80] B[128x80]
    constexpr int PITCH = 80;
    constexpr int A_TILE = 128 * PITCH;          // 10240
    constexpr int OFF_AL = A_TILE;
    constexpr int OFF_B  = 2 * A_TILE;
    constexpr int STAGE  = 3 * A_TILE;           // 30720
    extern __shared__ char smem[];
    const uint32_t sb = smem_u32(smem);

    const int tid = threadIdx.x;
    const int wid = tid >> 5;
    const int lane = tid & 31;
    const int g = lane >> 2;
    const int tig = lane & 3;
    const int warp_m = (wid & 3) * 32;
    const int warp_n = (wid >> 2) * 64;
    const int m0 = blockIdx.y * 128;
    const int n0 = blockIdx.x * 128;

    const __half* Ah = (const __half*)Ah_;
    const __half* Al = (const __half*)Al_;
    const __half* Wh = (const __half*)Wh_;

    float acc[2][8][4];
#pragma unroll
    for (int mt = 0; mt < 2; mt++)
#pragma unroll
        for (int nt = 0; nt < 8; nt++)
#pragma unroll
            for (int j = 0; j < 4; j++) acc[mt][nt][j] = 0.0f;

    const int NK = K / 32;
    const int crow = tid >> 2;                   // 0..63
    const int cchk = tid & 3;                    // 16B chunk (8 halfs)

    auto issue = [&](int it, int s) {
        const int kt = it * 32 + cchk * 8;
        const uint32_t st = sb + (uint32_t)s * STAGE;
#pragma unroll
        for (int i = 0; i < 2; i++) {
            int r = crow + i * 64;
            uint32_t so = (uint32_t)(r * PITCH + cchk * 16);
            const size_t ga = (size_t)(m0 + r) * K + kt;
            cpa16(st + so, Ah + ga);
            cpa16(st + OFF_AL + so, Al + ga);
            cpa16(st + OFF_B + so, Wh + (size_t)(n0 + r) * K + kt);
        }
        asm volatile("cp.async.commit_group;" ::: "memory");
    };

    issue(0, 0);
    if (NK > 1) issue(1, 1);

    const uint32_t lrow = (uint32_t)(lane & 15);
    const uint32_t lchk = (uint32_t)(lane >> 4) * 16;

    for (int it = 0; it < NK; it++) {
        if (it + 1 < NK) {
            asm volatile("cp.async.wait_group 1;" ::: "memory");
        } else {
            asm volatile("cp.async.wait_group 0;" ::: "memory");
        }
        __syncthreads();
        if (it + 2 < NK) issue(it + 2, (it + 2) % 3);

        const uint32_t st = sb + (uint32_t)(it % 3) * STAGE;
        const uint32_t abase = st + (uint32_t)(warp_m + lrow) * PITCH + lchk;
        const uint32_t bbase = st + OFF_B + (uint32_t)(warp_n + lrow) * PITCH + lchk;

#pragma unroll
        for (int kk = 0; kk < 2; kk++) {
            uint32_t ah[2][4], al[2][4];
#pragma unroll
            for (int mt = 0; mt < 2; mt++) {
                uint32_t ao = abase + (uint32_t)(mt * 16 * PITCH + kk * 32);
                ldsm4(ah[mt][0], ah[mt][1], ah[mt][2], ah[mt][3], ao);
                ldsm4(al[mt][0], al[mt][1], al[mt][2], al[mt][3], ao + OFF_AL);
            }
            uint32_t b[8][2];
#pragma unroll
            for (int p = 0; p < 4; p++) {
                uint32_t bo = bbase + (uint32_t)(p * 16 * PITCH + kk * 32);
                uint32_t r0, r1, r2, r3;
                ldsm4(r0, r1, r2, r3, bo);
                b[2 * p][0] = r0; b[2 * p][1] = r2;
                b[2 * p + 1][0] = r1; b[2 * p + 1][1] = r3;
            }
#pragma unroll
            for (int nt = 0; nt < 8; nt++)
#pragma unroll
                for (int mt = 0; mt < 2; mt++)
                    mma_f16(acc[mt][nt], ah[mt], b[nt][0], b[nt][1]);
#pragma unroll
            for (int nt = 0; nt < 8; nt++)
#pragma unroll
                for (int mt = 0; mt < 2; mt++)
                    mma_f16(acc[mt][nt], al[mt], b[nt][0], b[nt][1]);
        }
    }

    // epilogue (fp32 out)
#pragma unroll
    for (int mt = 0; mt < 2; mt++) {
        int mA = m0 + warp_m + mt * 16 + g;
#pragma unroll
        for (int nt = 0; nt < 8; nt++) {
            int n = n0 + warp_n + nt * 8 + 2 * tig;
            float e0 = acc[mt][nt][0], e1 = acc[mt][nt][1];
            float e2 = acc[mt][nt][2], e3 = acc[mt][nt][3];
            if (MODE == 0) {
                if (n < relu_upto)     { e0 = fmaxf(e0, 0.f); e2 = fmaxf(e2, 0.f); }
                if (n + 1 < relu_upto) { e1 = fmaxf(e1, 0.f); e3 = fmaxf(e3, 0.f); }
            } else {
                float bb0 = bias[n], bb1 = bias[n + 1];
                e0 += bb0; e1 += bb1; e2 += bb0; e3 += bb1;
            }
            *(float2*)(C + (size_t)mA * Nn + n)       = make_float2(e0, e1);
            *(float2*)(C + (size_t)(mA + 8) * Nn + n) = make_float2(e2, e3);
        }
    }
}

// ---------------------------------------------------------------------------
// vk partial reduction (unchanged)
// ---------------------------------------------------------------------------
__global__ __launch_bounds__(256) void vk_partial_kernel(
    const float* __restrict__ qkv, float* __restrict__ part)
{
    const int blk = blockIdx.x;
    const int slice = blk & 7;
    const int head = blk >> 3;
    const int b = head >> 5;
    const int hh = head & 31;
    const int tid = threadIdx.x;

    __shared__ float ks[8][32];
    __shared__ float vs[8][32];

    float acc[5] = {0.f, 0.f, 0.f, 0.f, 0.f};

    const float* base = qkv + (size_t)b * Nx * NC3 + (size_t)(slice * 512) * NC3 + hh * 32;
    const int r = tid >> 5;
    const int e = tid & 31;

    for (int n0 = 0; n0 < 512; n0 += 8) {
        const float* p = base + (size_t)(n0 + r) * NC3 + e;
        float kreg = p[1024];
        float vreg = p[2048];
        __syncthreads();
        ks[r][e] = kreg;
        vs[r][e] = vreg;
        __syncthreads();
#pragma unroll
        for (int rr = 0; rr < 8; rr++) {
#pragma unroll
            for (int i = 0; i < 5; i++) {
                int idx = tid + 256 * i;
                if (idx < 1056) {
                    int d = idx >> 5;
                    int ee = idx & 31;
                    float vval = (d == 32) ? 1.0f : vs[rr][d];
                    acc[i] += vval * ks[rr][ee];
                }
            }
        }
    }
#pragma unroll
    for (int i = 0; i < 5; i++) {
        int idx = tid + 256 * i;
        if (idx < 1056) part[(size_t)blk * 1056 + idx] = acc[i];
    }
}

__global__ void vk_reduce_kernel(const float* __restrict__ part,
                                 float* __restrict__ vk)
{
    int idx = blockIdx.x * 256 + threadIdx.x;
    if (idx >= 128 * 1056) return;
    int head = idx / 1056;
    int j = idx % 1056;
    float s = 0.f;
#pragma unroll
    for (int sl = 0; sl < 8; sl++)
        s += part[(size_t)(head * 8 + sl) * 1056 + j];
    vk[idx] = s;
}

// ---------------------------------------------------------------------------
// att kernel: normalize, write split fp16 hi/lo planes (GEMM2 A operand)
// ---------------------------------------------------------------------------
__global__ __launch_bounds__(128) void att_kernel(
    const float* __restrict__ qkv, const float* __restrict__ vk,
    uint32_t* __restrict__ ath, uint32_t* __restrict__ atl)
{
    const int blk = blockIdx.x;
    const int nch = blk & 31;
    const int head = blk >> 5;
    const int b = head >> 5;
    const int hh = head & 31;
    const int tid = threadIdx.x;

    __shared__ float vks[1056];
    __shared__ float qs[128][33];
    __shared__ uint32_t sh[128][17];
    __shared__ uint32_t sl[128][17];

    for (int i = tid; i < 1056; i += 128)
        vks[i] = vk[(size_t)head * 1056 + i];

    const float* qbase = qkv + (size_t)b * Nx * NC3 + (size_t)(nch * 128) * NC3 + hh * 32;
#pragma unroll
    for (int i = 0; i < 32; i++) {
        int idx = i * 128 + tid;
        int row = idx >> 5;
        int e = idx & 31;
        qs[row][e] = qbase[(size_t)row * NC3 + e];
    }
    __syncthreads();

    float qr[32];
#pragma unroll
    for (int e = 0; e < 32; e++) qr[e] = qs[tid][e];

    float den = 0.f;
#pragma unroll
    for (int e = 0; e < 32; e++) den += vks[1024 + e] * qr[e];
    float inv = 1.0f / (den + EPSV);

#pragma unroll
    for (int w = 0; w < 16; w++) {
        float s0 = 0.f, s1 = 0.f;
#pragma unroll
        for (int e = 0; e < 32; e++) {
            s0 += vks[(2 * w) * 32 + e] * qr[e];
            s1 += vks[(2 * w + 1) * 32 + e] * qr[e];
        }
        uint32_t hw, lw;
        split_pair(s0 * inv, s1 * inv, hw, lw);
        sh[tid][w] = hw;
        sl[tid][w] = lw;
    }
    __syncthreads();

    const size_t rowbase = (size_t)b * Nx + (size_t)nch * 128;
#pragma unroll
    for (int i = 0; i < 16; i++) {
        int idx = i * 128 + tid;
        int row = idx >> 4;
        int w = idx & 15;
        size_t o = (rowbase + row) * 512 + hh * 16 + w;
        ath[o] = sh[row][w];
        atl[o] = sl[row][w];
    }
}

// ---------------------------------------------------------------------------
extern "C" void kernel_launch(void* const* d_in, const int* in_sizes, int n_in,
                              void* d_out, int out_size)
{
    const float* x     = (const float*)d_in[0];
    const float* Wqkv  = (const float*)d_in[1];
    const float* Wproj = (const float*)d_in[2];
    const float* bproj = (const float*)d_in[3];
    float* out = (float*)d_out;

    float *qkv, *part, *vk;
    uint32_t *xh, *xl, *ath, *atl, *wqh, *wph;
    cudaGetSymbolAddress((void**)&qkv,  g_qkv);
    cudaGetSymbolAddress((void**)&part, g_vkpart);
    cudaGetSymbolAddress((void**)&vk,   g_vk);
    cudaGetSymbolAddress((void**)&xh,   g_xh);
    cudaGetSymbolAddress((void**)&xl,   g_xl);
    cudaGetSymbolAddress((void**)&ath,  g_ath);
    cudaGetSymbolAddress((void**)&atl,  g_atl);
    cudaGetSymbolAddress((void**)&wqh,  g_wqh);
    cudaGetSymbolAddress((void**)&wph,  g_wph);

    const int M = Bx * Nx;   // 16384

    const int smem = 3 * 30720;   // 92160 B per CTA (2 CTAs/SM)
    cudaFuncSetAttribute(f16_gemm<0>,
                         cudaFuncAttributeMaxDynamicSharedMemorySize, smem);
    cudaFuncSetAttribute(f16_gemm<1>,
                         cudaFuncAttributeMaxDynamicSharedMemorySize, smem);

    // 0) operand prep: x -> hi/lo fp16 planes, weights -> single fp16
    {
        int np;
        np = M * Cx / 2;
        split2_kernel<<<(np + 255) / 256, 256>>>(x, xh, xl, np);
        np = NC3 * Cx / 2;
        round1_kernel<<<(np + 255) / 256, 256>>>(Wqkv, wqh, np);
        np = Cx * Cx / 2;
        round1_kernel<<<(np + 255) / 256, 256>>>(Wproj, wph, np);
    }

    // 1) qkv = x @ Wqkv^T (fp16 A-split 2-chain), relu on n < 2048
    f16_gemm<0><<<dim3(NC3 / 128, M / 128), 256, smem>>>(
        xh, xl, wqh, qkv, nullptr, M, NC3, Cx, 2 * Cx);

    // 2) vk partials + reduce
    vk_partial_kernel<<<1024, 256>>>(qkv, part);
    vk_reduce_kernel<<<(128 * 1056 + 255) / 256, 256>>>(part, vk);

    // 3) attention normalize -> att hi/lo planes
    att_kernel<<<4096, 128>>>(qkv, vk, ath, atl);

    // 4) out = att @ Wproj^T + b  (fp16 A-split 2-chain)
    f16_gemm<1><<<dim3(Cx / 128, M / 128), 256, smem>>>(
        ath, atl, wph, out, bproj, M, Cx, Cx, 0);
}